// round 10
// baseline (speedup 1.0000x reference)
#include <cuda_runtime.h>
#include <cuda_fp16.h>
#include <cstdint>

// ---------------------------------------------------------------------------
// Problem constants
// ---------------------------------------------------------------------------
#define M_TOT 16384   // 8 * 2048
#define N_TOT 4096
#define K_TOT 4096
#define BXQ 4
#define BYQ 4
#define NCQ 256
#define BSQ 8
#define OUT_DIM 1024
#define IN_DIM  1024
#define NUM_BLK 128
#define JDIM (NUM_BLK * OUT_DIM)  // 131072

// GEMM tiling: CTA 128x128x64, 8 warps (2x4), warp tile 64x32, 3 stages
#define BM 128
#define BN 128
#define BK 64
#define KT_STEPS (K_TOT / BK)     // 64
#define STAGES 3

#define ST_A 0
#define ST_B (16 * 1024)
#define STAGE_SZ (32 * 1024)
#define SMEM_DYN (STAGES * STAGE_SZ)   // 96 KB -> 2 CTAs/SM

// Fused prep grid split
#define CONV_BLOCKS 32768   // x convert: 32768*256 threads, 8 floats each
#define RECON_BLOCKS 8192   // W reconstruct: 8192*256 = 2,097,152 code blocks

// ---------------------------------------------------------------------------
// Scratch (device globals; allocation-free rule)
// ---------------------------------------------------------------------------
__device__ __half g_A[(size_t)M_TOT * K_TOT];   // x as fp16, row-major [M,K]
__device__ __half g_W[(size_t)N_TOT * K_TOT];   // reconstructed W fp16 [N,K]

// ---------------------------------------------------------------------------
// Helpers
// ---------------------------------------------------------------------------
__device__ __forceinline__ uint32_t smem_u32(const void* p) {
    uint32_t a;
    asm("{ .reg .u64 t; cvta.to.shared.u64 t, %1; cvt.u32.u64 %0, t; }" : "=r"(a) : "l"(p));
    return a;
}
// L1-bypass cp.async ONLY (R8 lesson: .ca steals L1/shared pipe from ldmatrix)
__device__ __forceinline__ void cp16(uint32_t saddr, const void* gaddr) {
    asm volatile("cp.async.cg.shared.global [%0], [%1], 16;" :: "r"(saddr), "l"(gaddr) : "memory");
}
__device__ __forceinline__ void ldsm_x4(uint32_t addr, uint32_t& r0, uint32_t& r1,
                                        uint32_t& r2, uint32_t& r3) {
    asm volatile("ldmatrix.sync.aligned.m8n8.x4.shared.b16 {%0,%1,%2,%3}, [%4];"
                 : "=r"(r0), "=r"(r1), "=r"(r2), "=r"(r3) : "r"(addr));
}
__device__ __forceinline__ void mma16816(float* c, const uint32_t* a, const uint32_t* b) {
    asm volatile("mma.sync.aligned.m16n8k16.row.col.f32.f16.f16.f32 "
                 "{%0,%1,%2,%3}, {%4,%5,%6,%7}, {%8,%9}, {%0,%1,%2,%3};"
                 : "+f"(c[0]), "+f"(c[1]), "+f"(c[2]), "+f"(c[3])
                 : "r"(a[0]), "r"(a[1]), "r"(a[2]), "r"(a[3]), "r"(b[0]), "r"(b[1]));
}
// evict-first fp32x2 store (output is dead data; don't displace operand tiles in L2)
__device__ __forceinline__ void stg_cs_v2(float* p, float x, float y) {
    asm volatile("st.global.cs.v2.f32 [%0], {%1, %2};" :: "l"(p), "f"(x), "f"(y) : "memory");
}
// streaming fp32x4 load (x fp32 is never re-read after conversion)
__device__ __forceinline__ float4 ldg_cs_v4(const float4* p) {
    float4 v;
    asm volatile("ld.global.cs.v4.f32 {%0,%1,%2,%3}, [%4];"
                 : "=f"(v.x), "=f"(v.y), "=f"(v.z), "=f"(v.w) : "l"(p));
    return v;
}

// ---------------------------------------------------------------------------
// Fused prep: blocks [0, CONV_BLOCKS) convert x fp32->fp16;
//             blocks [CONV_BLOCKS, ...) reconstruct W from PQ codebook.
// ---------------------------------------------------------------------------
__global__ void prep_kernel(const float4* __restrict__ x,
                            const float* __restrict__ centroids,
                            const int* __restrict__ assignments) {
    if (blockIdx.x < CONV_BLOCKS) {
        size_t i = (size_t)blockIdx.x * blockDim.x + threadIdx.x;
        float4 v0 = ldg_cs_v4(x + 2 * i);
        float4 v1 = ldg_cs_v4(x + 2 * i + 1);
        __half2 h[4];
        h[0] = __halves2half2(__float2half_rn(v0.x), __float2half_rn(v0.y));
        h[1] = __halves2half2(__float2half_rn(v0.z), __float2half_rn(v0.w));
        h[2] = __halves2half2(__float2half_rn(v1.x), __float2half_rn(v1.y));
        h[3] = __halves2half2(__float2half_rn(v1.z), __float2half_rn(v1.w));
        reinterpret_cast<uint4*>(g_A)[i] = *reinterpret_cast<uint4*>(h);
    } else {
        int idx = (blockIdx.x - CONV_BLOCKS) * blockDim.x + threadIdx.x;
        int j  = idx % JDIM;
        int by = (idx / JDIM) % BYQ;
        int bx = idx / (JDIM * BYQ);
        int nb = j / OUT_DIM;
        int od = j % OUT_DIM;
        int a  = assignments[idx];

        const float4* c = reinterpret_cast<const float4*>(
            centroids + ((((size_t)bx * BYQ + by) * NCQ + a) * BSQ));
        float4 c0 = c[0], c1 = c[1];

        size_t o  = (size_t)bx * OUT_DIM + od;
        size_t ii = (size_t)by * IN_DIM + (size_t)nb * BSQ;
        __half2 h[4];
        h[0] = __halves2half2(__float2half_rn(c0.x), __float2half_rn(c0.y));
        h[1] = __halves2half2(__float2half_rn(c0.z), __float2half_rn(c0.w));
        h[2] = __halves2half2(__float2half_rn(c1.x), __float2half_rn(c1.y));
        h[3] = __halves2half2(__float2half_rn(c1.z), __float2half_rn(c1.w));
        *reinterpret_cast<uint4*>(g_W + o * K_TOT + ii) = *reinterpret_cast<uint4*>(h);
    }
}

// ---------------------------------------------------------------------------
// GEMM: C[m,n] = sum_k A[m,k]*W[n,k] + bias[n]   (fp16 HMMA, fp32 accum)
// 128x128x64 CTA tile, 8 warps (2x4), warp tile 64x32, 3-stage cp.async.
// ---------------------------------------------------------------------------
__device__ __forceinline__ void load_stage(uint32_t sb, int buf, int kt,
                                           int m0, int n0, int tid) {
    const uint32_t stg = sb + (uint32_t)buf * STAGE_SZ;
    const int kofs = kt * BK;
#pragma unroll
    for (int j = 0; j < 4; j++) {
        int i = tid + 256 * j;
        int row = i >> 3, ch = i & 7;
        uint32_t soff = (uint32_t)(row * 128) + (uint32_t)((ch ^ (row & 7)) << 4);
        cp16(stg + ST_A + soff, g_A + (size_t)(m0 + row) * K_TOT + kofs + ch * 8);
        cp16(stg + ST_B + soff, g_W + (size_t)(n0 + row) * K_TOT + kofs + ch * 8);
    }
    asm volatile("cp.async.commit_group;" ::: "memory");
}

__global__ __launch_bounds__(256, 2)
void hgemm_kernel(const float* __restrict__ bias, float* __restrict__ C) {
    extern __shared__ char smem_raw[];
    const uint32_t sb = smem_u32(smem_raw);

    const int tid = threadIdx.x;
    const int wid = tid >> 5;
    const int lane = tid & 31;
    const int warp_m = wid >> 2;     // 0..1
    const int warp_n = wid & 3;      // 0..3
    const int m0 = blockIdx.y * BM;
    const int n0 = blockIdx.x * BN;

    float acc[4][4][4];
#pragma unroll
    for (int i = 0; i < 4; i++)
#pragma unroll
        for (int j = 0; j < 4; j++)
#pragma unroll
            for (int e = 0; e < 4; e++) acc[i][j][e] = 0.f;

    // prologue
    load_stage(sb, 0, 0, m0, n0, tid);
    load_stage(sb, 1, 1, m0, n0, tid);

    // prefetch bias while pipeline fills (L2-resident, off the critical path)
    float rb0[4], rb1[4];
#pragma unroll
    for (int nf = 0; nf < 4; nf++) {
        const int col = n0 + warp_n * 32 + nf * 8 + (lane & 3) * 2;
        rb0[nf] = bias[col];
        rb1[nf] = bias[col + 1];
    }

    // ldmatrix lane addressing
    const int a_row = warp_m * 64 + (lane & 15);                       // + mf*16
    const int a_csel = lane >> 4;                                      // 16B-chunk parity
    const int b_row = warp_n * 32 + (lane & 7) + ((lane & 16) >> 1);   // + bp*16
    const int b_csel = (lane & 8) >> 3;

#pragma unroll 3
    for (int kt = 0; kt < KT_STEPS; kt++) {
        if (kt + 2 < KT_STEPS) asm volatile("cp.async.wait_group 1;" ::: "memory");
        else                   asm volatile("cp.async.wait_group 0;" ::: "memory");
        __syncthreads();   // single barrier per iter (3-stage: write target never aliases live reads)

        if (kt + 2 < KT_STEPS)
            load_stage(sb, (kt + 2) % STAGES, kt + 2, m0, n0, tid);

        const uint32_t stg = sb + (uint32_t)(kt % STAGES) * STAGE_SZ;
#pragma unroll
        for (int s = 0; s < 4; s++) {
            uint32_t a[4][4], b[4][2];
            const int ac = s * 2 + a_csel;
            const int bc = s * 2 + b_csel;
#pragma unroll
            for (int mf = 0; mf < 4; mf++) {
                int row = a_row + mf * 16;
                uint32_t addr = stg + ST_A + row * 128 + ((ac ^ (row & 7)) << 4);
                ldsm_x4(addr, a[mf][0], a[mf][1], a[mf][2], a[mf][3]);
            }
#pragma unroll
            for (int bp = 0; bp < 2; bp++) {
                int row = b_row + bp * 16;
                uint32_t addr = stg + ST_B + row * 128 + ((bc ^ (row & 7)) << 4);
                ldsm_x4(addr, b[2 * bp][0], b[2 * bp][1], b[2 * bp + 1][0], b[2 * bp + 1][1]);
            }
#pragma unroll
            for (int mf = 0; mf < 4; mf++)
#pragma unroll
                for (int nf = 0; nf < 4; nf++)
                    mma16816(acc[mf][nf], a[mf], b[nf]);
        }
    }

    // epilogue: bias add + evict-first store (don't pollute L2 operand tiles)
#pragma unroll
    for (int nf = 0; nf < 4; nf++) {
        const int col = n0 + warp_n * 32 + nf * 8 + (lane & 3) * 2;
#pragma unroll
        for (int mf = 0; mf < 4; mf++) {
            const int row = m0 + warp_m * 64 + mf * 16 + (lane >> 2);
            stg_cs_v2(C + (size_t)row * N_TOT + col,
                      acc[mf][nf][0] + rb0[nf], acc[mf][nf][1] + rb1[nf]);
            stg_cs_v2(C + (size_t)(row + 8) * N_TOT + col,
                      acc[mf][nf][2] + rb0[nf], acc[mf][nf][3] + rb1[nf]);
        }
    }
}

// ---------------------------------------------------------------------------
// kernel_launch
//   0: x f32 [8,2048,4096]  1: centroids f32 [4,4,256,8]  2: bias f32 [4096]
//   3: assignments i32 [4,4,131072]  4/5: sample dims (full 4096)
// ---------------------------------------------------------------------------
extern "C" void kernel_launch(void* const* d_in, const int* in_sizes, int n_in,
                              void* d_out, int out_size) {
    const float* x           = (const float*)d_in[0];
    const float* centroids   = (const float*)d_in[1];
    const float* bias        = (const float*)d_in[2];
    const int*   assignments = (const int*)d_in[3];
    float* out = (float*)d_out;

    cudaFuncSetAttribute(hgemm_kernel,
                         cudaFuncAttributeMaxDynamicSharedMemorySize, SMEM_DYN);

    // 1) fused prep: x -> fp16  ||  reconstruct W -> fp16
    prep_kernel<<<CONV_BLOCKS + RECON_BLOCKS, 256>>>(
        reinterpret_cast<const float4*>(x), centroids, assignments);

    // 2) tensor-core GEMM + bias
    dim3 grid(N_TOT / BN, M_TOT / BM);   // (32, 128)
    hgemm_kernel<<<grid, 256, SMEM_DYN>>>(bias, out);
}

// round 11
// speedup vs baseline: 1.0002x; 1.0002x over previous
#include <cuda_runtime.h>
#include <cuda_fp16.h>
#include <cstdint>

// ---------------------------------------------------------------------------
// Problem constants
// ---------------------------------------------------------------------------
#define M_TOT 16384   // 8 * 2048
#define N_TOT 4096
#define K_TOT 4096
#define BXQ 4
#define BYQ 4
#define NCQ 256
#define BSQ 8
#define OUT_DIM 1024
#define IN_DIM  1024
#define NUM_BLK 128
#define JDIM (NUM_BLK * OUT_DIM)  // 131072

// GEMM tiling: CTA 128x128x64, 8 warps (2x4), warp tile 64x32, 3 stages
#define BM 128
#define BN 128
#define BK 64
#define KT_STEPS (K_TOT / BK)     // 64
#define STAGES 3

#define ST_A 0
#define ST_B (16 * 1024)
#define STAGE_SZ (32 * 1024)
#define SMEM_DYN (STAGES * STAGE_SZ)   // 96 KB -> 2 CTAs/SM

// Fused prep grid split
#define CONV_BLOCKS 32768   // x convert: 32768*256 threads, 8 floats each
#define RECON_BLOCKS 8192   // W reconstruct: 8192*256 = 2,097,152 code blocks

// ---------------------------------------------------------------------------
// Scratch (device globals; allocation-free rule)
// ---------------------------------------------------------------------------
__device__ __half g_A[(size_t)M_TOT * K_TOT];   // x as fp16, row-major [M,K]
__device__ __half g_W[(size_t)N_TOT * K_TOT];   // reconstructed W fp16 [N,K]

// ---------------------------------------------------------------------------
// Helpers
// ---------------------------------------------------------------------------
__device__ __forceinline__ uint32_t smem_u32(const void* p) {
    uint32_t a;
    asm("{ .reg .u64 t; cvta.to.shared.u64 t, %1; cvt.u32.u64 %0, t; }" : "=r"(a) : "l"(p));
    return a;
}
// L1-bypass cp.async ONLY (R8 lesson: .ca steals L1/shared pipe from ldmatrix)
__device__ __forceinline__ void cp16(uint32_t saddr, const void* gaddr) {
    asm volatile("cp.async.cg.shared.global [%0], [%1], 16;" :: "r"(saddr), "l"(gaddr) : "memory");
}
__device__ __forceinline__ void ldsm_x4(uint32_t addr, uint32_t& r0, uint32_t& r1,
                                        uint32_t& r2, uint32_t& r3) {
    asm volatile("ldmatrix.sync.aligned.m8n8.x4.shared.b16 {%0,%1,%2,%3}, [%4];"
                 : "=r"(r0), "=r"(r1), "=r"(r2), "=r"(r3) : "r"(addr));
}
__device__ __forceinline__ void mma16816(float* c, const uint32_t* a, const uint32_t* b) {
    asm volatile("mma.sync.aligned.m16n8k16.row.col.f32.f16.f16.f32 "
                 "{%0,%1,%2,%3}, {%4,%5,%6,%7}, {%8,%9}, {%0,%1,%2,%3};"
                 : "+f"(c[0]), "+f"(c[1]), "+f"(c[2]), "+f"(c[3])
                 : "r"(a[0]), "r"(a[1]), "r"(a[2]), "r"(a[3]), "r"(b[0]), "r"(b[1]));
}

// ---------------------------------------------------------------------------
// Fused prep: blocks [0, CONV_BLOCKS) convert x fp32->fp16;
//             blocks [CONV_BLOCKS, ...) reconstruct W from PQ codebook.
// ---------------------------------------------------------------------------
__global__ void prep_kernel(const float4* __restrict__ x,
                            const float* __restrict__ centroids,
                            const int* __restrict__ assignments) {
    if (blockIdx.x < CONV_BLOCKS) {
        size_t i = (size_t)blockIdx.x * blockDim.x + threadIdx.x;
        float4 v0 = x[2 * i];
        float4 v1 = x[2 * i + 1];
        __half2 h[4];
        h[0] = __halves2half2(__float2half_rn(v0.x), __float2half_rn(v0.y));
        h[1] = __halves2half2(__float2half_rn(v0.z), __float2half_rn(v0.w));
        h[2] = __halves2half2(__float2half_rn(v1.x), __float2half_rn(v1.y));
        h[3] = __halves2half2(__float2half_rn(v1.z), __float2half_rn(v1.w));
        reinterpret_cast<uint4*>(g_A)[i] = *reinterpret_cast<uint4*>(h);
    } else {
        int idx = (blockIdx.x - CONV_BLOCKS) * blockDim.x + threadIdx.x;
        int j  = idx % JDIM;
        int by = (idx / JDIM) % BYQ;
        int bx = idx / (JDIM * BYQ);
        int nb = j / OUT_DIM;
        int od = j % OUT_DIM;
        int a  = assignments[idx];

        const float4* c = reinterpret_cast<const float4*>(
            centroids + ((((size_t)bx * BYQ + by) * NCQ + a) * BSQ));
        float4 c0 = c[0], c1 = c[1];

        size_t o  = (size_t)bx * OUT_DIM + od;
        size_t ii = (size_t)by * IN_DIM + (size_t)nb * BSQ;
        __half2 h[4];
        h[0] = __halves2half2(__float2half_rn(c0.x), __float2half_rn(c0.y));
        h[1] = __halves2half2(__float2half_rn(c0.z), __float2half_rn(c0.w));
        h[2] = __halves2half2(__float2half_rn(c1.x), __float2half_rn(c1.y));
        h[3] = __halves2half2(__float2half_rn(c1.z), __float2half_rn(c1.w));
        *reinterpret_cast<uint4*>(g_W + o * K_TOT + ii) = *reinterpret_cast<uint4*>(h);
    }
}

// ---------------------------------------------------------------------------
// GEMM: C[m,n] = sum_k A[m,k]*W[n,k] + bias[n]   (fp16 HMMA, fp32 accum)
// 128x128x64 CTA tile, 8 warps (2x4), warp tile 64x32, 3-stage cp.async.
// ---------------------------------------------------------------------------
__device__ __forceinline__ void load_stage(uint32_t sb, int buf, int kt,
                                           int m0, int n0, int tid) {
    const uint32_t stg = sb + (uint32_t)buf * STAGE_SZ;
    const int kofs = kt * BK;
#pragma unroll
    for (int j = 0; j < 4; j++) {
        int i = tid + 256 * j;
        int row = i >> 3, ch = i & 7;
        uint32_t soff = (uint32_t)(row * 128) + (uint32_t)((ch ^ (row & 7)) << 4);
        cp16(stg + ST_A + soff, g_A + (size_t)(m0 + row) * K_TOT + kofs + ch * 8);
        cp16(stg + ST_B + soff, g_W + (size_t)(n0 + row) * K_TOT + kofs + ch * 8);
    }
    asm volatile("cp.async.commit_group;" ::: "memory");
}

__global__ __launch_bounds__(256, 2)
void hgemm_kernel(const float* __restrict__ bias, float* __restrict__ C) {
    extern __shared__ char smem_raw[];
    const uint32_t sb = smem_u32(smem_raw);

    const int tid = threadIdx.x;
    const int wid = tid >> 5;
    const int lane = tid & 31;
    const int warp_m = wid >> 2;     // 0..1
    const int warp_n = wid & 3;      // 0..3
    const int m0 = blockIdx.y * BM;
    const int n0 = blockIdx.x * BN;

    float acc[4][4][4];
#pragma unroll
    for (int i = 0; i < 4; i++)
#pragma unroll
        for (int j = 0; j < 4; j++)
#pragma unroll
            for (int e = 0; e < 4; e++) acc[i][j][e] = 0.f;

    // prologue
    load_stage(sb, 0, 0, m0, n0, tid);
    load_stage(sb, 1, 1, m0, n0, tid);

    // prefetch bias while pipeline fills (L2-resident, off the critical path)
    float rb0[4], rb1[4];
#pragma unroll
    for (int nf = 0; nf < 4; nf++) {
        const int col = n0 + warp_n * 32 + nf * 8 + (lane & 3) * 2;
        rb0[nf] = bias[col];
        rb1[nf] = bias[col + 1];
    }

    // ldmatrix lane addressing
    const int a_row = warp_m * 64 + (lane & 15);                       // + mf*16
    const int a_csel = lane >> 4;                                      // 16B-chunk parity
    const int b_row = warp_n * 32 + (lane & 7) + ((lane & 16) >> 1);   // + bp*16
    const int b_csel = (lane & 8) >> 3;

#pragma unroll 3
    for (int kt = 0; kt < KT_STEPS; kt++) {
        if (kt + 2 < KT_STEPS) asm volatile("cp.async.wait_group 1;" ::: "memory");
        else                   asm volatile("cp.async.wait_group 0;" ::: "memory");
        __syncthreads();   // single barrier per iter (3-stage: write target never aliases live reads)

        if (kt + 2 < KT_STEPS)
            load_stage(sb, (kt + 2) % STAGES, kt + 2, m0, n0, tid);

        const uint32_t stg = sb + (uint32_t)(kt % STAGES) * STAGE_SZ;
#pragma unroll
        for (int s = 0; s < 4; s++) {
            uint32_t a[4][4], b[4][2];
            const int ac = s * 2 + a_csel;
            const int bc = s * 2 + b_csel;
#pragma unroll
            for (int mf = 0; mf < 4; mf++) {
                int row = a_row + mf * 16;
                uint32_t addr = stg + ST_A + row * 128 + ((ac ^ (row & 7)) << 4);
                ldsm_x4(addr, a[mf][0], a[mf][1], a[mf][2], a[mf][3]);
            }
#pragma unroll
            for (int bp = 0; bp < 2; bp++) {
                int row = b_row + bp * 16;
                uint32_t addr = stg + ST_B + row * 128 + ((bc ^ (row & 7)) << 4);
                ldsm_x4(addr, b[2 * bp][0], b[2 * bp][1], b[2 * bp + 1][0], b[2 * bp + 1][1]);
            }
#pragma unroll
            for (int mf = 0; mf < 4; mf++)
#pragma unroll
                for (int nf = 0; nf < 4; nf++)
                    mma16816(acc[mf][nf], a[mf], b[nf]);
        }
    }

    // epilogue: bias add + store fp32
#pragma unroll
    for (int nf = 0; nf < 4; nf++) {
        const int col = n0 + warp_n * 32 + nf * 8 + (lane & 3) * 2;
#pragma unroll
        for (int mf = 0; mf < 4; mf++) {
            const int row = m0 + warp_m * 64 + mf * 16 + (lane >> 2);
            float2 v0 = make_float2(acc[mf][nf][0] + rb0[nf], acc[mf][nf][1] + rb1[nf]);
            float2 v1 = make_float2(acc[mf][nf][2] + rb0[nf], acc[mf][nf][3] + rb1[nf]);
            *reinterpret_cast<float2*>(C + (size_t)row * N_TOT + col) = v0;
            *reinterpret_cast<float2*>(C + (size_t)(row + 8) * N_TOT + col) = v1;
        }
    }
}

// ---------------------------------------------------------------------------
// kernel_launch
//   0: x f32 [8,2048,4096]  1: centroids f32 [4,4,256,8]  2: bias f32 [4096]
//   3: assignments i32 [4,4,131072]  4/5: sample dims (full 4096)
// ---------------------------------------------------------------------------
extern "C" void kernel_launch(void* const* d_in, const int* in_sizes, int n_in,
                              void* d_out, int out_size) {
    const float* x           = (const float*)d_in[0];
    const float* centroids   = (const float*)d_in[1];
    const float* bias        = (const float*)d_in[2];
    const int*   assignments = (const int*)d_in[3];
    float* out = (float*)d_out;

    cudaFuncSetAttribute(hgemm_kernel,
                         cudaFuncAttributeMaxDynamicSharedMemorySize, SMEM_DYN);

    // 1) fused prep: x -> fp16  ||  reconstruct W -> fp16
    prep_kernel<<<CONV_BLOCKS + RECON_BLOCKS, 256>>>(
        reinterpret_cast<const float4*>(x), centroids, assignments);

    // 2) tensor-core GEMM + bias
    dim3 grid(N_TOT / BN, M_TOT / BM);   // (32, 128)
    hgemm_kernel<<<grid, 256, SMEM_DYN>>>(bias, out);
}

// round 12
// speedup vs baseline: 1.0315x; 1.0313x over previous
#include <cuda_runtime.h>
#include <cuda_fp16.h>
#include <cstdint>

// ---------------------------------------------------------------------------
// Problem constants
// ---------------------------------------------------------------------------
#define M_TOT 16384   // 8 * 2048
#define N_TOT 4096
#define K_TOT 4096
#define BXQ 4
#define BYQ 4
#define NCQ 256
#define BSQ 8
#define OUT_DIM 1024
#define IN_DIM  1024
#define NUM_BLK 128
#define JDIM (NUM_BLK * OUT_DIM)  // 131072

// GEMM tiling: CTA 128x128x64, 8 warps (2x4), warp tile 64x32, 3 stages
#define BM 128
#define BN 128
#define BK 64
#define KT_STEPS (K_TOT / BK)     // 64
#define STAGES 3

#define ST_A 0
#define ST_B (16 * 1024)
#define STAGE_SZ (32 * 1024)
#define SMEM_DYN (STAGES * STAGE_SZ)   // 96 KB -> 2 CTAs/SM

// Fused prep grid split
#define CONV_BLOCKS 32768   // x convert: 32768*256 threads, 8 floats each
#define RECON_BLOCKS 8192   // W reconstruct: 8192*256 = 2,097,152 code blocks

// ---------------------------------------------------------------------------
// Scratch (device globals; allocation-free rule)
// ---------------------------------------------------------------------------
__device__ __half g_A[(size_t)M_TOT * K_TOT];   // x as fp16, row-major [M,K]
__device__ __half g_W[(size_t)N_TOT * K_TOT];   // reconstructed W fp16 [N,K]

// ---------------------------------------------------------------------------
// Helpers
// ---------------------------------------------------------------------------
__device__ __forceinline__ uint32_t smem_u32(const void* p) {
    uint32_t a;
    asm("{ .reg .u64 t; cvta.to.shared.u64 t, %1; cvt.u32.u64 %0, t; }" : "=r"(a) : "l"(p));
    return a;
}
// L1-bypass cp.async ONLY (R8 lesson: .ca steals L1/shared pipe from ldmatrix)
__device__ __forceinline__ void cp16(uint32_t saddr, const void* gaddr) {
    asm volatile("cp.async.cg.shared.global [%0], [%1], 16;" :: "r"(saddr), "l"(gaddr) : "memory");
}
__device__ __forceinline__ void ldsm_x4(uint32_t addr, uint32_t& r0, uint32_t& r1,
                                        uint32_t& r2, uint32_t& r3) {
    asm volatile("ldmatrix.sync.aligned.m8n8.x4.shared.b16 {%0,%1,%2,%3}, [%4];"
                 : "=r"(r0), "=r"(r1), "=r"(r2), "=r"(r3) : "r"(addr));
}
__device__ __forceinline__ void mma16816(float* c, const uint32_t* a, const uint32_t* b) {
    asm volatile("mma.sync.aligned.m16n8k16.row.col.f32.f16.f16.f32 "
                 "{%0,%1,%2,%3}, {%4,%5,%6,%7}, {%8,%9}, {%0,%1,%2,%3};"
                 : "+f"(c[0]), "+f"(c[1]), "+f"(c[2]), "+f"(c[3])
                 : "r"(a[0]), "r"(a[1]), "r"(a[2]), "r"(a[3]), "r"(b[0]), "r"(b[1]));
}

// ---------------------------------------------------------------------------
// Fused prep: blocks [0, CONV_BLOCKS) convert x fp32->fp16;
//             blocks [CONV_BLOCKS, ...) reconstruct W from PQ codebook.
// ---------------------------------------------------------------------------
__global__ void prep_kernel(const float4* __restrict__ x,
                            const float* __restrict__ centroids,
                            const int* __restrict__ assignments) {
    if (blockIdx.x < CONV_BLOCKS) {
        size_t i = (size_t)blockIdx.x * blockDim.x + threadIdx.x;
        float4 v0 = x[2 * i];
        float4 v1 = x[2 * i + 1];
        __half2 h[4];
        h[0] = __halves2half2(__float2half_rn(v0.x), __float2half_rn(v0.y));
        h[1] = __halves2half2(__float2half_rn(v0.z), __float2half_rn(v0.w));
        h[2] = __halves2half2(__float2half_rn(v1.x), __float2half_rn(v1.y));
        h[3] = __halves2half2(__float2half_rn(v1.z), __float2half_rn(v1.w));
        reinterpret_cast<uint4*>(g_A)[i] = *reinterpret_cast<uint4*>(h);
    } else {
        int idx = (blockIdx.x - CONV_BLOCKS) * blockDim.x + threadIdx.x;
        int j  = idx % JDIM;
        int by = (idx / JDIM) % BYQ;
        int bx = idx / (JDIM * BYQ);
        int nb = j / OUT_DIM;
        int od = j % OUT_DIM;
        int a  = assignments[idx];

        const float4* c = reinterpret_cast<const float4*>(
            centroids + ((((size_t)bx * BYQ + by) * NCQ + a) * BSQ));
        float4 c0 = c[0], c1 = c[1];

        size_t o  = (size_t)bx * OUT_DIM + od;
        size_t ii = (size_t)by * IN_DIM + (size_t)nb * BSQ;
        __half2 h[4];
        h[0] = __halves2half2(__float2half_rn(c0.x), __float2half_rn(c0.y));
        h[1] = __halves2half2(__float2half_rn(c0.z), __float2half_rn(c0.w));
        h[2] = __halves2half2(__float2half_rn(c1.x), __float2half_rn(c1.y));
        h[3] = __halves2half2(__float2half_rn(c1.z), __float2half_rn(c1.w));
        *reinterpret_cast<uint4*>(g_W + o * K_TOT + ii) = *reinterpret_cast<uint4*>(h);
    }
}

// ---------------------------------------------------------------------------
// GEMM: C[m,n] = sum_k A[m,k]*W[n,k] + bias[n]   (fp16 HMMA, fp32 accum)
// 128x128x64 CTA tile, 8 warps (2x4), warp tile 64x32, 3-stage cp.async,
// B-fragment double buffering across the 4 k16 sub-steps.
// ---------------------------------------------------------------------------
__device__ __forceinline__ void load_stage(uint32_t sb, int buf, int kt,
                                           int m0, int n0, int tid) {
    const uint32_t stg = sb + (uint32_t)buf * STAGE_SZ;
    const int kofs = kt * BK;
#pragma unroll
    for (int j = 0; j < 4; j++) {
        int i = tid + 256 * j;
        int row = i >> 3, ch = i & 7;
        uint32_t soff = (uint32_t)(row * 128) + (uint32_t)((ch ^ (row & 7)) << 4);
        cp16(stg + ST_A + soff, g_A + (size_t)(m0 + row) * K_TOT + kofs + ch * 8);
        cp16(stg + ST_B + soff, g_W + (size_t)(n0 + row) * K_TOT + kofs + ch * 8);
    }
    asm volatile("cp.async.commit_group;" ::: "memory");
}

__global__ __launch_bounds__(256, 2)
void hgemm_kernel(const float* __restrict__ bias, float* __restrict__ C) {
    extern __shared__ char smem_raw[];
    const uint32_t sb = smem_u32(smem_raw);

    const int tid = threadIdx.x;
    const int wid = tid >> 5;
    const int lane = tid & 31;
    const int warp_m = wid >> 2;     // 0..1
    const int warp_n = wid & 3;      // 0..3
    const int m0 = blockIdx.y * BM;
    const int n0 = blockIdx.x * BN;

    float acc[4][4][4];
#pragma unroll
    for (int i = 0; i < 4; i++)
#pragma unroll
        for (int j = 0; j < 4; j++)
#pragma unroll
            for (int e = 0; e < 4; e++) acc[i][j][e] = 0.f;

    // prologue
    load_stage(sb, 0, 0, m0, n0, tid);
    load_stage(sb, 1, 1, m0, n0, tid);

    // ldmatrix lane addressing
    const int a_row = warp_m * 64 + (lane & 15);                       // + mf*16
    const int a_csel = lane >> 4;                                      // 16B-chunk parity
    const int b_row0 = warp_n * 32 + (lane & 7) + ((lane & 16) >> 1);  // bp=0
    const int b_row1 = b_row0 + 16;                                    // bp=1
    const int b_csel = (lane & 8) >> 3;

#pragma unroll 3
    for (int kt = 0; kt < KT_STEPS; kt++) {
        if (kt + 2 < KT_STEPS) asm volatile("cp.async.wait_group 1;" ::: "memory");
        else                   asm volatile("cp.async.wait_group 0;" ::: "memory");
        __syncthreads();   // single barrier per iter (3-stage: write target never aliases live reads)

        if (kt + 2 < KT_STEPS)
            load_stage(sb, (kt + 2) % STAGES, kt + 2, m0, n0, tid);

        const uint32_t stg = sb + (uint32_t)(kt % STAGES) * STAGE_SZ;

        // preload B fragments for s=0
        uint32_t bcur[4][2], bnxt[4][2];
        {
            const int bc = b_csel;
            ldsm_x4(stg + ST_B + b_row0 * 128 + ((bc ^ (b_row0 & 7)) << 4),
                    bcur[0][0], bcur[0][1], bcur[1][0], bcur[1][1]);
            ldsm_x4(stg + ST_B + b_row1 * 128 + ((bc ^ (b_row1 & 7)) << 4),
                    bcur[2][0], bcur[2][1], bcur[3][0], bcur[3][1]);
        }

#pragma unroll
        for (int s = 0; s < 4; s++) {
            uint32_t a[4][4];
            const int ac = s * 2 + a_csel;
#pragma unroll
            for (int mf = 0; mf < 4; mf++) {
                int row = a_row + mf * 16;
                uint32_t addr = stg + ST_A + row * 128 + ((ac ^ (row & 7)) << 4);
                ldsm_x4(addr, a[mf][0], a[mf][1], a[mf][2], a[mf][3]);
            }
            // issue next step's B loads before this step's MMAs (latency hiding)
            if (s < 3) {
                const int bc = (s + 1) * 2 + b_csel;
                ldsm_x4(stg + ST_B + b_row0 * 128 + ((bc ^ (b_row0 & 7)) << 4),
                        bnxt[0][0], bnxt[0][1], bnxt[1][0], bnxt[1][1]);
                ldsm_x4(stg + ST_B + b_row1 * 128 + ((bc ^ (b_row1 & 7)) << 4),
                        bnxt[2][0], bnxt[2][1], bnxt[3][0], bnxt[3][1]);
            }
#pragma unroll
            for (int mf = 0; mf < 4; mf++)
#pragma unroll
                for (int nf = 0; nf < 4; nf++)
                    mma16816(acc[mf][nf], a[mf], bcur[nf]);
            if (s < 3) {
#pragma unroll
                for (int nf = 0; nf < 4; nf++) {
                    bcur[nf][0] = bnxt[nf][0];
                    bcur[nf][1] = bnxt[nf][1];
                }
            }
        }
    }

    // epilogue: bias add + store fp32
#pragma unroll
    for (int nf = 0; nf < 4; nf++) {
        const int col = n0 + warp_n * 32 + nf * 8 + (lane & 3) * 2;
        const float b0 = bias[col];
        const float b1 = bias[col + 1];
#pragma unroll
        for (int mf = 0; mf < 4; mf++) {
            const int row = m0 + warp_m * 64 + mf * 16 + (lane >> 2);
            float2 v0 = make_float2(acc[mf][nf][0] + b0, acc[mf][nf][1] + b1);
            float2 v1 = make_float2(acc[mf][nf][2] + b0, acc[mf][nf][3] + b1);
            *reinterpret_cast<float2*>(C + (size_t)row * N_TOT + col) = v0;
            *reinterpret_cast<float2*>(C + (size_t)(row + 8) * N_TOT + col) = v1;
        }
    }
}

// ---------------------------------------------------------------------------
// kernel_launch
//   0: x f32 [8,2048,4096]  1: centroids f32 [4,4,256,8]  2: bias f32 [4096]
//   3: assignments i32 [4,4,131072]  4/5: sample dims (full 4096)
// ---------------------------------------------------------------------------
extern "C" void kernel_launch(void* const* d_in, const int* in_sizes, int n_in,
                              void* d_out, int out_size) {
    const float* x           = (const float*)d_in[0];
    const float* centroids   = (const float*)d_in[1];
    const float* bias        = (const float*)d_in[2];
    const int*   assignments = (const int*)d_in[3];
    float* out = (float*)d_out;

    cudaFuncSetAttribute(hgemm_kernel,
                         cudaFuncAttributeMaxDynamicSharedMemorySize, SMEM_DYN);

    // 1) fused prep: x -> fp16  ||  reconstruct W -> fp16
    prep_kernel<<<CONV_BLOCKS + RECON_BLOCKS, 256>>>(
        reinterpret_cast<const float4*>(x), centroids, assignments);

    // 2) tensor-core GEMM + bias
    dim3 grid(N_TOT / BN, M_TOT / BM);   // (32, 128)
    hgemm_kernel<<<grid, 256, SMEM_DYN>>>(bias, out);
}